// round 12
// baseline (speedup 1.0000x reference)
#include <cuda_runtime.h>
#include <cuda_fp16.h>
#include <math.h>
#include <stdint.h>

// Problem constants
#define BATCH 4
#define SEQ   2048
#define DIM   2048
#define NHEADS 32
#define HDIM  64
#define MTOT  (BATCH * SEQ) // 8192

// Scratch (device globals: allocation-free)
__device__ float  g_h[(size_t)MTOT * DIM];   // input-projection output (f32)
__device__ __half g_s[(size_t)MTOT * DIM];   // rnn states (fp16)
__device__ __half g_x[(size_t)MTOT * DIM];   // x (fp16)
__device__ __half g_w1[(size_t)DIM * DIM];   // w_in (fp16)
__device__ __half g_w2[(size_t)DIM * DIM];   // w_out * norm_weight (fp16)
__device__ float  g_scale[MTOT];             // per-row rmsnorm scale

// ---------------------------------------------------------------------------
// helpers
// ---------------------------------------------------------------------------
__device__ __forceinline__ uint32_t smem_u32(const void* p) {
    uint32_t a;
    asm("{ .reg .u64 t; cvta.to.shared.u64 t, %1; cvt.u32.u64 %0, t; }"
        : "=r"(a) : "l"(p));
    return a;
}

#define CP_ASYNC16(dst, src) \
    asm volatile("cp.async.cg.shared.global [%0], [%1], 16;" \
                 :: "r"(dst), "l"(src) : "memory")
#define CP_COMMIT() asm volatile("cp.async.commit_group;" ::: "memory")
#define CP_WAIT(n)  asm volatile("cp.async.wait_group %0;" :: "n"(n) : "memory")

__device__ __forceinline__ void mma_f16(float c[4],
    unsigned a0, unsigned a1, unsigned a2, unsigned a3,
    unsigned b0, unsigned b1)
{
    asm volatile(
        "mma.sync.aligned.m16n8k16.row.col.f32.f16.f16.f32 "
        "{%0,%1,%2,%3}, {%4,%5,%6,%7}, {%8,%9}, {%0,%1,%2,%3};"
        : "+f"(c[0]), "+f"(c[1]), "+f"(c[2]), "+f"(c[3])
        : "r"(a0), "r"(a1), "r"(a2), "r"(a3), "r"(b0), "r"(b1));
}

__device__ __forceinline__ void ldsm_x4(
    unsigned& r0, unsigned& r1, unsigned& r2, unsigned& r3, uint32_t addr)
{
    asm volatile(
        "ldmatrix.sync.aligned.m8n8.x4.shared.b16 {%0,%1,%2,%3}, [%4];"
        : "=r"(r0), "=r"(r1), "=r"(r2), "=r"(r3) : "r"(addr));
}

__device__ __forceinline__ unsigned long long fma_f32x2(
    unsigned long long a, unsigned long long b, unsigned long long c)
{
    unsigned long long d;
    asm("fma.rn.f32x2 %0, %1, %2, %3;" : "=l"(d) : "l"(a), "l"(b), "l"(c));
    return d;
}

__device__ __forceinline__ unsigned long long add_f32x2(
    unsigned long long a, unsigned long long b)
{
    unsigned long long d;
    asm("add.rn.f32x2 %0, %1, %2;" : "=l"(d) : "l"(a), "l"(b));
    return d;
}

__device__ __forceinline__ unsigned long long pack2(float lo, float hi) {
    unsigned long long r;
    asm("mov.b64 %0, {%1, %2};" : "=l"(r) : "f"(lo), "f"(hi));
    return r;
}

__device__ __forceinline__ void unpack2(float& lo, float& hi, unsigned long long v) {
    asm("mov.b64 {%0, %1}, %2;" : "=f"(lo), "=f"(hi) : "l"(v));
}

__device__ __forceinline__ float tanh_fast(float z) {
    float r;
    asm("tanh.approx.f32 %0, %1;" : "=f"(r) : "f"(z));
    return r;
}

// ---------------------------------------------------------------------------
// FP16 mma.sync GEMM (fp32 accumulate), cp.async 4-stage, 1 sync/chunk,
// 2 CTAs/SM, ldmatrix with precomputed flat smem addresses.  (proven R8-R11)
// ---------------------------------------------------------------------------
#define GBM 128
#define GBN 128
#define GBK 32
#define NSTAGE 4
#define SKH 40                   // 80B row stride -> ldsm conflict-free
#define ABYTES (GBM * SKH * 2)   // 10240
#define STGB   (2 * ABYTES)      // 20480 per stage
#define NCHUNK (DIM / GBK)       // 64

__global__ __launch_bounds__(256, 2)
void gemm_h_kernel(const __half* __restrict__ A, const __half* __restrict__ B,
                   const float* __restrict__ bias, float* __restrict__ C,
                   const float* __restrict__ rowScale)
{
    extern __shared__ __half smem[];
    const uint32_t sb = smem_u32(smem);

    const int tid  = threadIdx.x;
    const int lane = tid & 31;
    const int wid  = tid >> 5;
    const int cRow = blockIdx.y * GBM;
    const int cCol = blockIdx.x * GBN;

    const int m0  = (wid & 1) * 64;
    const int n0  = (wid >> 1) * 32;
    const int gid = lane >> 2;
    const int tg  = lane & 3;

    const int aRowOff = lane & 15;
    const int aColOff = (lane >> 4) * 8;
    const int bRowOff = ((lane >> 4) & 1) * 8 + (lane & 7);
    const int bColOff = ((lane >> 3) & 1) * 8;
    const uint32_t aOff = sb + (uint32_t)((m0 + aRowOff) * SKH + aColOff) * 2;
    const uint32_t bOff = sb + ABYTES + (uint32_t)((n0 + bRowOff) * SKH + bColOff) * 2;

    float acc[4][4][4];
#pragma unroll
    for (int mf = 0; mf < 4; mf++)
#pragma unroll
        for (int nf = 0; nf < 4; nf++)
#pragma unroll
            for (int i = 0; i < 4; i++) acc[mf][nf][i] = 0.f;

    const int lrow  = tid >> 2;
    const int lslot = tid & 3;
    const __half* aSrc = A + (size_t)(cRow + lrow) * DIM + 8 * lslot;
    const __half* bSrc = B + (size_t)(cCol + lrow) * DIM + 8 * lslot;
    const uint32_t ldst = sb + (uint32_t)(lrow * SKH + 8 * lslot) * 2;
    const size_t rowJump = (size_t)64 * DIM;

    auto load_chunk = [&](int c, int s) {
        if (c < NCHUNK) {
            const size_t k = (size_t)c * GBK;
            const uint32_t d = ldst + (uint32_t)s * STGB;
            CP_ASYNC16(d,                      aSrc + k);
            CP_ASYNC16(d + 64 * SKH * 2,       aSrc + k + rowJump);
            CP_ASYNC16(d + ABYTES,             bSrc + k);
            CP_ASYNC16(d + ABYTES + 64*SKH*2,  bSrc + k + rowJump);
        }
        CP_COMMIT();
    };

    for (int s = 0; s < NSTAGE - 1; s++) load_chunk(s, s);

    for (int c = 0; c < NCHUNK; c++) {
        const int s = c & (NSTAGE - 1);
        CP_WAIT(NSTAGE - 2);
        __syncthreads();
        load_chunk(c + NSTAGE - 1, (c + NSTAGE - 1) & (NSTAGE - 1));

        const uint32_t aS = aOff + (uint32_t)s * STGB;
        const uint32_t bS = bOff + (uint32_t)s * STGB;

#pragma unroll
        for (int ks = 0; ks < 2; ks++) {
            const uint32_t kb = 32 * ks;
            unsigned a[4][4], b[4][2];
#pragma unroll
            for (int mf = 0; mf < 4; mf++)
                ldsm_x4(a[mf][0], a[mf][1], a[mf][2], a[mf][3],
                        aS + kb + (uint32_t)mf * (16 * SKH * 2));
#pragma unroll
            for (int p = 0; p < 2; p++)
                ldsm_x4(b[2*p][0], b[2*p][1], b[2*p+1][0], b[2*p+1][1],
                        bS + kb + (uint32_t)p * (16 * SKH * 2));
#pragma unroll
            for (int mf = 0; mf < 4; mf++)
#pragma unroll
                for (int nf = 0; nf < 4; nf++)
                    mma_f16(acc[mf][nf], a[mf][0], a[mf][1], a[mf][2], a[mf][3],
                            b[nf][0], b[nf][1]);
        }
    }

#pragma unroll
    for (int mf = 0; mf < 4; mf++) {
        const int row = cRow + m0 + 16 * mf + gid;
        const float rs0 = rowScale ? rowScale[row] : 1.f;
        const float rs1 = rowScale ? rowScale[row + 8] : 1.f;
#pragma unroll
        for (int nf = 0; nf < 4; nf++) {
            const int col = cCol + n0 + 8 * nf + 2 * tg;
            float b0 = 0.f, b1 = 0.f;
            if (bias) { b0 = bias[col]; b1 = bias[col + 1]; }
            float2 v0 = make_float2(acc[mf][nf][0] * rs0 + b0, acc[mf][nf][1] * rs0 + b1);
            float2 v1 = make_float2(acc[mf][nf][2] * rs1 + b0, acc[mf][nf][3] * rs1 + b1);
            *(float2*)(C + (size_t)row * DIM + col) = v0;
            *(float2*)(C + (size_t)(row + 8) * DIM + col) = v1;
        }
    }
}

// ---------------------------------------------------------------------------
// f32 -> fp16 conversions (8 elems/thread); colscale folds norm_weight
// ---------------------------------------------------------------------------
__global__ __launch_bounds__(256) void cvt_h_kernel(
    const float* __restrict__ in, __half* __restrict__ out)
{
    const size_t i = ((size_t)blockIdx.x * 256 + threadIdx.x) * 8;
    const float4 v0 = *(const float4*)(in + i);
    const float4 v1 = *(const float4*)(in + i + 4);
    __half2 h[4];
    h[0] = __floats2half2_rn(v0.x, v0.y);
    h[1] = __floats2half2_rn(v0.z, v0.w);
    h[2] = __floats2half2_rn(v1.x, v1.y);
    h[3] = __floats2half2_rn(v1.z, v1.w);
    *(uint4*)(out + i) = *(const uint4*)h;
}

__global__ __launch_bounds__(256) void cvt_h_colscale_kernel(
    const float* __restrict__ in, const float* __restrict__ colw,
    __half* __restrict__ out)
{
    const size_t i = ((size_t)blockIdx.x * 256 + threadIdx.x) * 8;
    const int c = (int)(i & (DIM - 1));
    const float4 v0 = *(const float4*)(in + i);
    const float4 v1 = *(const float4*)(in + i + 4);
    const float4 g0 = *(const float4*)(colw + c);
    const float4 g1 = *(const float4*)(colw + c + 4);
    __half2 h[4];
    h[0] = __floats2half2_rn(v0.x * g0.x, v0.y * g0.y);
    h[1] = __floats2half2_rn(v0.z * g0.z, v0.w * g0.w);
    h[2] = __floats2half2_rn(v1.x * g1.x, v1.y * g1.y);
    h[3] = __floats2half2_rn(v1.z * g1.z, v1.w * g1.w);
    *(uint4*)(out + i) = *(const uint4*)h;
}

// ---------------------------------------------------------------------------
// RNN scan: WARP-SYNCHRONOUS — one warp per (b,n) scan, NO __syncthreads,
// NO shfl. Lane l owns outputs j=l and j=l+32 with full 64-MAC dot products
// (W columns resident: 64 f32x2 regs). All 64 states in smem, read by every
// lane via broadcast LDS.128. Double-buffered state + one __syncwarp/step.
// ---------------------------------------------------------------------------
__global__ __launch_bounds__(32, 1) void rnn_scan_kernel(
    const float* __restrict__ state_weight)
{
    const int b = blockIdx.x >> 5;
    const int n = blockIdx.x & 31;
    const int l = threadIdx.x;          // lane 0..31
    const int j0 = l, j1 = l + 32;

    __shared__ float s_sh[2][HDIM];

    // Wa[i] = (W[2i][j0], W[2i+1][j0]); Wb same for column j1
    unsigned long long Wa[32], Wb[32];
    const float* Wn = state_weight + (size_t)n * HDIM * HDIM;
#pragma unroll
    for (int i = 0; i < 32; i++) {
        Wa[i] = pack2(Wn[(2 * i) * HDIM + j0], Wn[(2 * i + 1) * HDIM + j0]);
        Wb[i] = pack2(Wn[(2 * i) * HDIM + j1], Wn[(2 * i + 1) * HDIM + j1]);
    }

    s_sh[0][j0] = 0.f;
    s_sh[0][j1] = 0.f;
    __syncwarp();

    const size_t base = ((size_t)b * SEQ) * DIM + n * HDIM;
    const float* gin = g_h + base;
    __half* gout = g_s + base;

    // depth-4 prefetch of x_t at both lane positions
    float pa[4], pb[4];
#pragma unroll
    for (int u = 0; u < 4; u++) {
        pa[u] = __ldg(gin + (size_t)u * DIM + j0);
        pb[u] = __ldg(gin + (size_t)u * DIM + j1);
    }
    const float* gpf = gin + 4 * DIM;

    int cur = 0;

#define SCAN_STEP(XA, XB, T)                                                 \
    do {                                                                     \
        const float4* sp = (const float4*)s_sh[cur];                         \
        unsigned long long a0, a1, a2, a3, b0, b1, b2, b3;                   \
        {                                                                    \
            const float4 v0 = sp[0], v1 = sp[1], v2 = sp[2], v3 = sp[3];     \
            const unsigned long long z = pack2(0.f, 0.f);                    \
            unsigned long long p0 = pack2(v0.x, v0.y), p1 = pack2(v0.z, v0.w);\
            unsigned long long p2 = pack2(v1.x, v1.y), p3 = pack2(v1.z, v1.w);\
            unsigned long long p4 = pack2(v2.x, v2.y), p5 = pack2(v2.z, v2.w);\
            unsigned long long p6 = pack2(v3.x, v3.y), p7 = pack2(v3.z, v3.w);\
            a0 = fma_f32x2(p0, Wa[0], z);  a1 = fma_f32x2(p1, Wa[1], z);     \
            a2 = fma_f32x2(p2, Wa[2], z);  a3 = fma_f32x2(p3, Wa[3], z);     \
            b0 = fma_f32x2(p0, Wb[0], z);  b1 = fma_f32x2(p1, Wb[1], z);     \
            b2 = fma_f32x2(p2, Wb[2], z);  b3 = fma_f32x2(p3, Wb[3], z);     \
            a0 = fma_f32x2(p4, Wa[4], a0); a1 = fma_f32x2(p5, Wa[5], a1);    \
            a2 = fma_f32x2(p6, Wa[6], a2); a3 = fma_f32x2(p7, Wa[7], a3);    \
            b0 = fma_f32x2(p4, Wb[4], b0); b1 = fma_f32x2(p5, Wb[5], b1);    \
            b2 = fma_f32x2(p6, Wb[6], b2); b3 = fma_f32x2(p7, Wb[7], b3);    \
        }                                                                    \
        _Pragma("unroll")                                                    \
        for (int q = 4; q < 16; q += 4) {                                    \
            const float4 v0 = sp[q], v1 = sp[q+1], v2 = sp[q+2], v3 = sp[q+3];\
            unsigned long long p0 = pack2(v0.x, v0.y), p1 = pack2(v0.z, v0.w);\
            unsigned long long p2 = pack2(v1.x, v1.y), p3 = pack2(v1.z, v1.w);\
            unsigned long long p4 = pack2(v2.x, v2.y), p5 = pack2(v2.z, v2.w);\
            unsigned long long p6 = pack2(v3.x, v3.y), p7 = pack2(v3.z, v3.w);\
            a0 = fma_f32x2(p0, Wa[2*q+0], a0); a1 = fma_f32x2(p1, Wa[2*q+1], a1);\
            a2 = fma_f32x2(p2, Wa[2*q+2], a2); a3 = fma_f32x2(p3, Wa[2*q+3], a3);\
            b0 = fma_f32x2(p0, Wb[2*q+0], b0); b1 = fma_f32x2(p1, Wb[2*q+1], b1);\
            b2 = fma_f32x2(p2, Wb[2*q+2], b2); b3 = fma_f32x2(p3, Wb[2*q+3], b3);\
            a0 = fma_f32x2(p4, Wa[2*q+4], a0); a1 = fma_f32x2(p5, Wa[2*q+5], a1);\
            a2 = fma_f32x2(p6, Wa[2*q+6], a2); a3 = fma_f32x2(p7, Wa[2*q+7], a3);\
            b0 = fma_f32x2(p4, Wb[2*q+4], b0); b1 = fma_f32x2(p5, Wb[2*q+5], b1);\
            b2 = fma_f32x2(p6, Wb[2*q+6], b2); b3 = fma_f32x2(p7, Wb[2*q+7], b3);\
        }                                                                    \
        unsigned long long sA = add_f32x2(add_f32x2(a0, a1), add_f32x2(a2, a3));\
        unsigned long long sB = add_f32x2(add_f32x2(b0, b1), add_f32x2(b2, b3));\
        float alo, ahi, blo, bhi;                                            \
        unpack2(alo, ahi, sA);                                               \
        unpack2(blo, bhi, sB);                                               \
        const float sv0 = tanh_fast(alo + ahi + (XA));                       \
        const float sv1 = tanh_fast(blo + bhi + (XB));                       \
        s_sh[cur ^ 1][j0] = sv0;                                             \
        s_sh[cur ^ 1][j1] = sv1;                                             \
        gout[(size_t)(T) * DIM + j0] = __float2half_rn(sv0);                 \
        gout[(size_t)(T) * DIM + j1] = __float2half_rn(sv1);                 \
        cur ^= 1;                                                            \
        __syncwarp();                                                        \
    } while (0)

    for (int t = 0; t < SEQ; t += 4) {
#pragma unroll
        for (int u = 0; u < 4; u++) {
            SCAN_STEP(pa[u], pb[u], t + u);
            const bool ok = (t + 4 + u < SEQ);
            pa[u] = ok ? __ldg(gpf + (size_t)u * DIM + j0) : 0.f;
            pb[u] = ok ? __ldg(gpf + (size_t)u * DIM + j1) : 0.f;
        }
        gpf += 4 * DIM;
    }
#undef SCAN_STEP
}

// ---------------------------------------------------------------------------
// Row scale: g_scale[row] = rsqrt(mean(states^2) + eps), reading fp16 states
// ---------------------------------------------------------------------------
__global__ __launch_bounds__(256) void row_scale_kernel()
{
    const int row = blockIdx.x;
    const __half* p = g_s + (size_t)row * DIM;
    const int t = threadIdx.x;

    const uint4 u = ((const uint4*)p)[t];
    const __half2* hp = (const __half2*)&u;
    float ss = 0.f;
#pragma unroll
    for (int i = 0; i < 4; i++) {
        float2 f = __half22float2(hp[i]);
        ss += f.x * f.x + f.y * f.y;
    }

#pragma unroll
    for (int off = 16; off > 0; off >>= 1)
        ss += __shfl_xor_sync(0xFFFFFFFFu, ss, off);

    __shared__ float red[8];
    const int warp = t >> 5;
    const int lane = t & 31;
    if (lane == 0) red[warp] = ss;
    __syncthreads();
    if (warp == 0) {
        float v = (lane < 8) ? red[lane] : 0.f;
#pragma unroll
        for (int off = 4; off > 0; off >>= 1)
            v += __shfl_xor_sync(0xFFFFFFFFu, v, off);
        if (lane == 0) g_scale[row] = rsqrtf(v * (1.0f / DIM) + 1e-6f);
    }
}

// ---------------------------------------------------------------------------
// Launch
// ---------------------------------------------------------------------------
extern "C" void kernel_launch(void* const* d_in, const int* in_sizes, int n_in,
                              void* d_out, int out_size)
{
    const float* x            = (const float*)d_in[0];
    const float* w_in         = (const float*)d_in[1];
    const float* b_in         = (const float*)d_in[2];
    const float* state_weight = (const float*)d_in[3];
    const float* norm_weight  = (const float*)d_in[4];
    const float* w_out        = (const float*)d_in[5];
    float* out = (float*)d_out;

    __half *gx, *gw1, *gw2, *gs;
    float *gh, *gscale;
    cudaGetSymbolAddress((void**)&gx,  g_x);
    cudaGetSymbolAddress((void**)&gw1, g_w1);
    cudaGetSymbolAddress((void**)&gw2, g_w2);
    cudaGetSymbolAddress((void**)&gh,  g_h);
    cudaGetSymbolAddress((void**)&gs,  g_s);
    cudaGetSymbolAddress((void**)&gscale, g_scale);

    const int SMEM_TOTAL = STGB * NSTAGE;   // 81920
    cudaFuncSetAttribute(gemm_h_kernel,
                         cudaFuncAttributeMaxDynamicSharedMemorySize, SMEM_TOTAL);

    // fp16 operand prep (norm_weight folded into w_out)
    cvt_h_kernel<<<(MTOT * DIM) / 2048, 256>>>(x, gx);
    cvt_h_kernel<<<(DIM * DIM) / 2048, 256>>>(w_in, gw1);
    cvt_h_colscale_kernel<<<(DIM * DIM) / 2048, 256>>>(w_out, norm_weight, gw2);

    dim3 ggrid(DIM / GBN, MTOT / GBM);   // (16, 64)

    gemm_h_kernel<<<ggrid, 256, SMEM_TOTAL>>>(gx, gw1, b_in, gh, nullptr);
    rnn_scan_kernel<<<BATCH * NHEADS, 32>>>(state_weight);
    row_scale_kernel<<<MTOT, 256>>>();
    gemm_h_kernel<<<ggrid, 256, SMEM_TOTAL>>>(gs, gw2, nullptr, out, gscale);
}

// round 13
// speedup vs baseline: 1.2612x; 1.2612x over previous
#include <cuda_runtime.h>
#include <cuda_fp16.h>
#include <math.h>
#include <stdint.h>

// Problem constants
#define BATCH 4
#define SEQ   2048
#define DIM   2048
#define NHEADS 32
#define HDIM  64
#define MTOT  (BATCH * SEQ) // 8192

// Scratch (device globals: allocation-free)
__device__ float  g_h[(size_t)MTOT * DIM];   // input-projection output (f32)
__device__ __half g_s[(size_t)MTOT * DIM];   // rnn states (fp16)
__device__ __half g_x[(size_t)MTOT * DIM];   // x (fp16)
__device__ __half g_w1[(size_t)DIM * DIM];   // w_in (fp16)
__device__ __half g_w2[(size_t)DIM * DIM];   // w_out * norm_weight (fp16)
__device__ float  g_scale[MTOT];             // per-row rmsnorm scale

// ---------------------------------------------------------------------------
// helpers
// ---------------------------------------------------------------------------
__device__ __forceinline__ uint32_t smem_u32(const void* p) {
    uint32_t a;
    asm("{ .reg .u64 t; cvta.to.shared.u64 t, %1; cvt.u32.u64 %0, t; }"
        : "=r"(a) : "l"(p));
    return a;
}

#define CP_ASYNC16(dst, src) \
    asm volatile("cp.async.cg.shared.global [%0], [%1], 16;" \
                 :: "r"(dst), "l"(src) : "memory")
#define CP_COMMIT() asm volatile("cp.async.commit_group;" ::: "memory")
#define CP_WAIT(n)  asm volatile("cp.async.wait_group %0;" :: "n"(n) : "memory")

__device__ __forceinline__ void mma_f16(float c[4],
    unsigned a0, unsigned a1, unsigned a2, unsigned a3,
    unsigned b0, unsigned b1)
{
    asm volatile(
        "mma.sync.aligned.m16n8k16.row.col.f32.f16.f16.f32 "
        "{%0,%1,%2,%3}, {%4,%5,%6,%7}, {%8,%9}, {%0,%1,%2,%3};"
        : "+f"(c[0]), "+f"(c[1]), "+f"(c[2]), "+f"(c[3])
        : "r"(a0), "r"(a1), "r"(a2), "r"(a3), "r"(b0), "r"(b1));
}

__device__ __forceinline__ void ldsm_x4(
    unsigned& r0, unsigned& r1, unsigned& r2, unsigned& r3, uint32_t addr)
{
    asm volatile(
        "ldmatrix.sync.aligned.m8n8.x4.shared.b16 {%0,%1,%2,%3}, [%4];"
        : "=r"(r0), "=r"(r1), "=r"(r2), "=r"(r3) : "r"(addr));
}

__device__ __forceinline__ unsigned long long fma_f32x2(
    unsigned long long a, unsigned long long b, unsigned long long c)
{
    unsigned long long d;
    asm("fma.rn.f32x2 %0, %1, %2, %3;" : "=l"(d) : "l"(a), "l"(b), "l"(c));
    return d;
}

__device__ __forceinline__ unsigned long long add_f32x2(
    unsigned long long a, unsigned long long b)
{
    unsigned long long d;
    asm("add.rn.f32x2 %0, %1, %2;" : "=l"(d) : "l"(a), "l"(b));
    return d;
}

__device__ __forceinline__ unsigned long long pack2(float lo, float hi) {
    unsigned long long r;
    asm("mov.b64 %0, {%1, %2};" : "=l"(r) : "f"(lo), "f"(hi));
    return r;
}

__device__ __forceinline__ void unpack2(float& lo, float& hi, unsigned long long v) {
    asm("mov.b64 {%0, %1}, %2;" : "=f"(lo), "=f"(hi) : "l"(v));
}

__device__ __forceinline__ float tanh_fast(float z) {
    float r;
    asm("tanh.approx.f32 %0, %1;" : "=f"(r) : "f"(z));
    return r;
}

// ---------------------------------------------------------------------------
// FP16 mma.sync GEMM (fp32 accumulate), cp.async 4-stage, 1 sync/chunk,
// 2 CTAs/SM, ldmatrix with precomputed flat smem addresses.  (proven R8-R11)
// ---------------------------------------------------------------------------
#define GBM 128
#define GBN 128
#define GBK 32
#define NSTAGE 4
#define SKH 40                   // 80B row stride -> ldsm conflict-free
#define ABYTES (GBM * SKH * 2)   // 10240
#define STGB   (2 * ABYTES)      // 20480 per stage
#define NCHUNK (DIM / GBK)       // 64

__global__ __launch_bounds__(256, 2)
void gemm_h_kernel(const __half* __restrict__ A, const __half* __restrict__ B,
                   const float* __restrict__ bias, float* __restrict__ C,
                   const float* __restrict__ rowScale)
{
    extern __shared__ __half smem[];
    const uint32_t sb = smem_u32(smem);

    const int tid  = threadIdx.x;
    const int lane = tid & 31;
    const int wid  = tid >> 5;
    const int cRow = blockIdx.y * GBM;
    const int cCol = blockIdx.x * GBN;

    const int m0  = (wid & 1) * 64;
    const int n0  = (wid >> 1) * 32;
    const int gid = lane >> 2;
    const int tg  = lane & 3;

    const int aRowOff = lane & 15;
    const int aColOff = (lane >> 4) * 8;
    const int bRowOff = ((lane >> 4) & 1) * 8 + (lane & 7);
    const int bColOff = ((lane >> 3) & 1) * 8;
    const uint32_t aOff = sb + (uint32_t)((m0 + aRowOff) * SKH + aColOff) * 2;
    const uint32_t bOff = sb + ABYTES + (uint32_t)((n0 + bRowOff) * SKH + bColOff) * 2;

    float acc[4][4][4];
#pragma unroll
    for (int mf = 0; mf < 4; mf++)
#pragma unroll
        for (int nf = 0; nf < 4; nf++)
#pragma unroll
            for (int i = 0; i < 4; i++) acc[mf][nf][i] = 0.f;

    const int lrow  = tid >> 2;
    const int lslot = tid & 3;
    const __half* aSrc = A + (size_t)(cRow + lrow) * DIM + 8 * lslot;
    const __half* bSrc = B + (size_t)(cCol + lrow) * DIM + 8 * lslot;
    const uint32_t ldst = sb + (uint32_t)(lrow * SKH + 8 * lslot) * 2;
    const size_t rowJump = (size_t)64 * DIM;

    auto load_chunk = [&](int c, int s) {
        if (c < NCHUNK) {
            const size_t k = (size_t)c * GBK;
            const uint32_t d = ldst + (uint32_t)s * STGB;
            CP_ASYNC16(d,                      aSrc + k);
            CP_ASYNC16(d + 64 * SKH * 2,       aSrc + k + rowJump);
            CP_ASYNC16(d + ABYTES,             bSrc + k);
            CP_ASYNC16(d + ABYTES + 64*SKH*2,  bSrc + k + rowJump);
        }
        CP_COMMIT();
    };

    for (int s = 0; s < NSTAGE - 1; s++) load_chunk(s, s);

    for (int c = 0; c < NCHUNK; c++) {
        const int s = c & (NSTAGE - 1);
        CP_WAIT(NSTAGE - 2);
        __syncthreads();
        load_chunk(c + NSTAGE - 1, (c + NSTAGE - 1) & (NSTAGE - 1));

        const uint32_t aS = aOff + (uint32_t)s * STGB;
        const uint32_t bS = bOff + (uint32_t)s * STGB;

#pragma unroll
        for (int ks = 0; ks < 2; ks++) {
            const uint32_t kb = 32 * ks;
            unsigned a[4][4], b[4][2];
#pragma unroll
            for (int mf = 0; mf < 4; mf++)
                ldsm_x4(a[mf][0], a[mf][1], a[mf][2], a[mf][3],
                        aS + kb + (uint32_t)mf * (16 * SKH * 2));
#pragma unroll
            for (int p = 0; p < 2; p++)
                ldsm_x4(b[2*p][0], b[2*p][1], b[2*p+1][0], b[2*p+1][1],
                        bS + kb + (uint32_t)p * (16 * SKH * 2));
#pragma unroll
            for (int mf = 0; mf < 4; mf++)
#pragma unroll
                for (int nf = 0; nf < 4; nf++)
                    mma_f16(acc[mf][nf], a[mf][0], a[mf][1], a[mf][2], a[mf][3],
                            b[nf][0], b[nf][1]);
        }
    }

#pragma unroll
    for (int mf = 0; mf < 4; mf++) {
        const int row = cRow + m0 + 16 * mf + gid;
        const float rs0 = rowScale ? rowScale[row] : 1.f;
        const float rs1 = rowScale ? rowScale[row + 8] : 1.f;
#pragma unroll
        for (int nf = 0; nf < 4; nf++) {
            const int col = cCol + n0 + 8 * nf + 2 * tg;
            float b0 = 0.f, b1 = 0.f;
            if (bias) { b0 = bias[col]; b1 = bias[col + 1]; }
            float2 v0 = make_float2(acc[mf][nf][0] * rs0 + b0, acc[mf][nf][1] * rs0 + b1);
            float2 v1 = make_float2(acc[mf][nf][2] * rs1 + b0, acc[mf][nf][3] * rs1 + b1);
            *(float2*)(C + (size_t)row * DIM + col) = v0;
            *(float2*)(C + (size_t)(row + 8) * DIM + col) = v1;
        }
    }
}

// ---------------------------------------------------------------------------
// f32 -> fp16 conversions (8 elems/thread); colscale folds norm_weight
// ---------------------------------------------------------------------------
__global__ __launch_bounds__(256) void cvt_h_kernel(
    const float* __restrict__ in, __half* __restrict__ out)
{
    const size_t i = ((size_t)blockIdx.x * 256 + threadIdx.x) * 8;
    const float4 v0 = *(const float4*)(in + i);
    const float4 v1 = *(const float4*)(in + i + 4);
    __half2 h[4];
    h[0] = __floats2half2_rn(v0.x, v0.y);
    h[1] = __floats2half2_rn(v0.z, v0.w);
    h[2] = __floats2half2_rn(v1.x, v1.y);
    h[3] = __floats2half2_rn(v1.z, v1.w);
    *(uint4*)(out + i) = *(const uint4*)h;
}

__global__ __launch_bounds__(256) void cvt_h_colscale_kernel(
    const float* __restrict__ in, const float* __restrict__ colw,
    __half* __restrict__ out)
{
    const size_t i = ((size_t)blockIdx.x * 256 + threadIdx.x) * 8;
    const int c = (int)(i & (DIM - 1));
    const float4 v0 = *(const float4*)(in + i);
    const float4 v1 = *(const float4*)(in + i + 4);
    const float4 g0 = *(const float4*)(colw + c);
    const float4 g1 = *(const float4*)(colw + c + 4);
    __half2 h[4];
    h[0] = __floats2half2_rn(v0.x * g0.x, v0.y * g0.y);
    h[1] = __floats2half2_rn(v0.z * g0.z, v0.w * g0.w);
    h[2] = __floats2half2_rn(v1.x * g1.x, v1.y * g1.y);
    h[3] = __floats2half2_rn(v1.z * g1.z, v1.w * g1.w);
    *(uint4*)(out + i) = *(const uint4*)h;
}

// ---------------------------------------------------------------------------
// RNN scan: 64 threads/CTA, ONE output per thread (full 64-MAC dot product,
// W column in 32 f32x2 regs), NO shfl on the chain. All threads read the
// shared state via broadcast LDS.128 (thread-uniform address, conflict-free).
// Single writer per state element. One 2-warp __syncthreads per step.
// Depth-8 input prefetch, fp16 state stores.
// ---------------------------------------------------------------------------
__global__ __launch_bounds__(64) void rnn_scan_kernel(
    const float* __restrict__ state_weight)
{
    const int b = blockIdx.x >> 5;
    const int n = blockIdx.x & 31;
    const int j = threadIdx.x;           // 0..63, owns output j

    __shared__ float s_sh[2][HDIM];

    // Wp[i] = (W[2i][j], W[2i+1][j]) — full column j resident
    unsigned long long Wp[32];
    const float* Wn = state_weight + (size_t)n * HDIM * HDIM;
#pragma unroll
    for (int i = 0; i < 32; i++)
        Wp[i] = pack2(Wn[(2 * i) * HDIM + j], Wn[(2 * i + 1) * HDIM + j]);

    s_sh[0][j] = 0.f;
    __syncthreads();

    const size_t base = ((size_t)b * SEQ) * DIM + n * HDIM + j;
    const float* gin = g_h + base;
    __half* gout = g_s + base;

    float pf[8];
#pragma unroll
    for (int u = 0; u < 8; u++) pf[u] = __ldg(gin + (size_t)u * DIM);
    const float* gpf = gin + 8 * DIM;

    int cur = 0;

#define SCAN_STEP(XT, T)                                                     \
    do {                                                                     \
        const float4* sp = (const float4*)s_sh[cur];                         \
        unsigned long long acc0, acc1, acc2, acc3;                           \
        {                                                                    \
            const float4 v0 = sp[0], v1 = sp[1], v2 = sp[2], v3 = sp[3];     \
            const unsigned long long z = pack2(0.f, 0.f);                    \
            acc0 = fma_f32x2(pack2(v0.x, v0.y), Wp[0], z);                   \
            acc1 = fma_f32x2(pack2(v0.z, v0.w), Wp[1], z);                   \
            acc2 = fma_f32x2(pack2(v1.x, v1.y), Wp[2], z);                   \
            acc3 = fma_f32x2(pack2(v1.z, v1.w), Wp[3], z);                   \
            acc0 = fma_f32x2(pack2(v2.x, v2.y), Wp[4], acc0);                \
            acc1 = fma_f32x2(pack2(v2.z, v2.w), Wp[5], acc1);                \
            acc2 = fma_f32x2(pack2(v3.x, v3.y), Wp[6], acc2);                \
            acc3 = fma_f32x2(pack2(v3.z, v3.w), Wp[7], acc3);                \
        }                                                                    \
        _Pragma("unroll")                                                    \
        for (int q = 4; q < 16; q += 4) {                                    \
            const float4 v0 = sp[q], v1 = sp[q+1], v2 = sp[q+2], v3 = sp[q+3];\
            acc0 = fma_f32x2(pack2(v0.x, v0.y), Wp[2*q + 0], acc0);          \
            acc1 = fma_f32x2(pack2(v0.z, v0.w), Wp[2*q + 1], acc1);          \
            acc2 = fma_f32x2(pack2(v1.x, v1.y), Wp[2*q + 2], acc2);          \
            acc3 = fma_f32x2(pack2(v1.z, v1.w), Wp[2*q + 3], acc3);          \
            acc0 = fma_f32x2(pack2(v2.x, v2.y), Wp[2*q + 4], acc0);          \
            acc1 = fma_f32x2(pack2(v2.z, v2.w), Wp[2*q + 5], acc1);          \
            acc2 = fma_f32x2(pack2(v3.x, v3.y), Wp[2*q + 6], acc2);          \
            acc3 = fma_f32x2(pack2(v3.z, v3.w), Wp[2*q + 7], acc3);          \
        }                                                                    \
        unsigned long long sT = add_f32x2(add_f32x2(acc0, acc1),             \
                                          add_f32x2(acc2, acc3));            \
        float lo, hi;                                                        \
        unpack2(lo, hi, sT);                                                 \
        const float sv = tanh_fast(lo + hi + (XT));                          \
        s_sh[cur ^ 1][j] = sv;                                               \
        gout[(size_t)(T) * DIM] = __float2half_rn(sv);                       \
        cur ^= 1;                                                            \
        __syncthreads();                                                     \
    } while (0)

    for (int t = 0; t < SEQ; t += 8) {
#pragma unroll
        for (int u = 0; u < 8; u++) {
            SCAN_STEP(pf[u], t + u);
            pf[u] = (t + 8 + u < SEQ) ? __ldg(gpf + (size_t)u * DIM) : 0.f;
        }
        gpf += 8 * DIM;
    }
#undef SCAN_STEP
}

// ---------------------------------------------------------------------------
// Row scale: g_scale[row] = rsqrt(mean(states^2) + eps), reading fp16 states
// ---------------------------------------------------------------------------
__global__ __launch_bounds__(256) void row_scale_kernel()
{
    const int row = blockIdx.x;
    const __half* p = g_s + (size_t)row * DIM;
    const int t = threadIdx.x;

    const uint4 u = ((const uint4*)p)[t];
    const __half2* hp = (const __half2*)&u;
    float ss = 0.f;
#pragma unroll
    for (int i = 0; i < 4; i++) {
        float2 f = __half22float2(hp[i]);
        ss += f.x * f.x + f.y * f.y;
    }

#pragma unroll
    for (int off = 16; off > 0; off >>= 1)
        ss += __shfl_xor_sync(0xFFFFFFFFu, ss, off);

    __shared__ float red[8];
    const int warp = t >> 5;
    const int lane = t & 31;
    if (lane == 0) red[warp] = ss;
    __syncthreads();
    if (warp == 0) {
        float v = (lane < 8) ? red[lane] : 0.f;
#pragma unroll
        for (int off = 4; off > 0; off >>= 1)
            v += __shfl_xor_sync(0xFFFFFFFFu, v, off);
        if (lane == 0) g_scale[row] = rsqrtf(v * (1.0f / DIM) + 1e-6f);
    }
}

// ---------------------------------------------------------------------------
// Launch
// ---------------------------------------------------------------------------
extern "C" void kernel_launch(void* const* d_in, const int* in_sizes, int n_in,
                              void* d_out, int out_size)
{
    const float* x            = (const float*)d_in[0];
    const float* w_in         = (const float*)d_in[1];
    const float* b_in         = (const float*)d_in[2];
    const float* state_weight = (const float*)d_in[3];
    const float* norm_weight  = (const float*)d_in[4];
    const float* w_out        = (const float*)d_in[5];
    float* out = (float*)d_out;

    __half *gx, *gw1, *gw2, *gs;
    float *gh, *gscale;
    cudaGetSymbolAddress((void**)&gx,  g_x);
    cudaGetSymbolAddress((void**)&gw1, g_w1);
    cudaGetSymbolAddress((void**)&gw2, g_w2);
    cudaGetSymbolAddress((void**)&gh,  g_h);
    cudaGetSymbolAddress((void**)&gs,  g_s);
    cudaGetSymbolAddress((void**)&gscale, g_scale);

    const int SMEM_TOTAL = STGB * NSTAGE;   // 81920
    cudaFuncSetAttribute(gemm_h_kernel,
                         cudaFuncAttributeMaxDynamicSharedMemorySize, SMEM_TOTAL);

    // fp16 operand prep (norm_weight folded into w_out)
    cvt_h_kernel<<<(MTOT * DIM) / 2048, 256>>>(x, gx);
    cvt_h_kernel<<<(DIM * DIM) / 2048, 256>>>(w_in, gw1);
    cvt_h_colscale_kernel<<<(DIM * DIM) / 2048, 256>>>(w_out, norm_weight, gw2);

    dim3 ggrid(DIM / GBN, MTOT / GBM);   // (16, 64)

    gemm_h_kernel<<<ggrid, 256, SMEM_TOTAL>>>(gx, gw1, b_in, gh, nullptr);
    rnn_scan_kernel<<<BATCH * NHEADS, 64>>>(state_weight);
    row_scale_kernel<<<MTOT, 256>>>();
    gemm_h_kernel<<<ggrid, 256, SMEM_TOTAL>>>(gs, gw2, nullptr, out, gscale);
}